// round 2
// baseline (speedup 1.0000x reference)
#include <cuda_runtime.h>
#include <math.h>

#define NN 50000
#define EE 500000

// node-space tables (float4 views of [N,128] / [N,2,192])
__device__ __align__(16) float4 g_q[NN * 32];
__device__ __align__(16) float4 g_k[NN * 32];
__device__ __align__(16) float4 g_v[NN * 32];
__device__ __align__(16) float4 g_z[NN * 96];      // [n][2][192]
// per-dst aggregates (zeroed every launch)
__device__ __align__(16) float4 g_aggT[NN * 32];   // [n][2][64]   sum w*enc
__device__ __align__(16) float4 g_aggM[NN * 64];   // [n][2][128]  sum w*msg
__device__ __align__(16) float4 g_aggV[NN * 32];   // [n][2][64]   sum w*v[src]
__device__ __align__(8)  float2 g_asum[NN];        // [n][2]       sum w
__device__ int g_is64;                             // edge_index dtype flag

static __device__ __forceinline__ float dot4(float4 a, float4 b) {
    return a.x * b.x + a.y * b.y + a.z * b.z + a.w * b.w;
}
static __device__ __forceinline__ void red4(float4* p, float x, float y, float z, float w) {
    asm volatile("red.global.add.v4.f32 [%0], {%1,%2,%3,%4};"
                 :: "l"(p), "f"(x), "f"(y), "f"(z), "f"(w) : "memory");
}
static __device__ __forceinline__ void red2(float2* p, float x, float y) {
    asm volatile("red.global.add.v2.f32 [%0], {%1,%2};"
                 :: "l"(p), "f"(x), "f"(y) : "memory");
}

// ---------------------------------------------------------------------------
// K0: detect edge_index dtype. JAX with x64 disabled silently produces int32
// even though the reference asks for int64. If the buffer is genuinely int64
// with node ids < 50000, every odd 32-bit word of the first 64 is zero; if
// int32, those words are random node ids (all-zero probability ~50000^-32).
// ---------------------------------------------------------------------------
__global__ void k_detect(const int* __restrict__ ei32) {
    int odd_or = 0;
    #pragma unroll
    for (int i = 1; i < 64; i += 2) odd_or |= ei32[i];
    g_is64 = (odd_or == 0) ? 1 : 0;
}

// ---------------------------------------------------------------------------
// K1: q,k,v,skip = x @ {Wq,Wk,Wv,Wskip} + bias.  Tile: 32 nodes x 128 cols,
// blockIdx.y selects the matrix. skip goes directly into d_out.
// ---------------------------------------------------------------------------
__global__ void k_node(const float* __restrict__ x,
                       const float* __restrict__ Wq, const float* __restrict__ bq,
                       const float* __restrict__ Wk, const float* __restrict__ bk,
                       const float* __restrict__ Wv, const float* __restrict__ bv,
                       const float* __restrict__ Ws, const float* __restrict__ bs,
                       float4* __restrict__ out_skip)
{
    const float* W; const float* B; float4* C;
    if      (blockIdx.y == 0) { W = Wq; B = bq; C = g_q; }
    else if (blockIdx.y == 1) { W = Wk; B = bk; C = g_k; }
    else if (blockIdx.y == 2) { W = Wv; B = bv; C = g_v; }
    else                      { W = Ws; B = bs; C = out_skip; }

    extern __shared__ float sm[];
    float* xs = sm;            // 32 x 128
    float* ws = sm + 32 * 128; // 128 x 128
    const int t = threadIdx.x;
    const int n0 = blockIdx.x * 32;

    const float4* x4 = (const float4*)x;
    for (int i = t; i < 32 * 32; i += 256) {
        int node = n0 + (i >> 5);
        ((float4*)xs)[i] = (node < NN) ? x4[(size_t)node * 32 + (i & 31)]
                                       : make_float4(0.f, 0.f, 0.f, 0.f);
    }
    const float4* W4 = (const float4*)W;
    for (int i = t; i < 128 * 32; i += 256) ((float4*)ws)[i] = W4[i];
    __syncthreads();

    const int c4 = (t & 31) * 4;
    const int r  = (t >> 5) * 4;
    float4 a0 = make_float4(0.f, 0.f, 0.f, 0.f), a1 = a0, a2 = a0, a3 = a0;
    const float* xr0 = xs + (r + 0) * 128;
    const float* xr1 = xs + (r + 1) * 128;
    const float* xr2 = xs + (r + 2) * 128;
    const float* xr3 = xs + (r + 3) * 128;

    #pragma unroll 8
    for (int k = 0; k < 128; k++) {
        float4 b = *(const float4*)&ws[k * 128 + c4];
        float v0 = xr0[k], v1 = xr1[k], v2 = xr2[k], v3 = xr3[k];
        a0.x += v0 * b.x; a0.y += v0 * b.y; a0.z += v0 * b.z; a0.w += v0 * b.w;
        a1.x += v1 * b.x; a1.y += v1 * b.y; a1.z += v1 * b.z; a1.w += v1 * b.w;
        a2.x += v2 * b.x; a2.y += v2 * b.y; a2.z += v2 * b.z; a2.w += v2 * b.w;
        a3.x += v3 * b.x; a3.y += v3 * b.y; a3.z += v3 * b.z; a3.w += v3 * b.w;
    }
    float4 bb = *(const float4*)&B[c4];
    a0.x += bb.x; a0.y += bb.y; a0.z += bb.z; a0.w += bb.w;
    a1.x += bb.x; a1.y += bb.y; a1.z += bb.z; a1.w += bb.w;
    a2.x += bb.x; a2.y += bb.y; a2.z += bb.z; a2.w += bb.w;
    a3.x += bb.x; a3.y += bb.y; a3.z += bb.z; a3.w += bb.w;

    const int f4 = t & 31;
    int nb = n0 + r;
    if (nb + 0 < NN) C[(size_t)(nb + 0) * 32 + f4] = a0;
    if (nb + 1 < NN) C[(size_t)(nb + 1) * 32 + f4] = a1;
    if (nb + 2 < NN) C[(size_t)(nb + 2) * 32 + f4] = a2;
    if (nb + 3 < NN) C[(size_t)(nb + 3) * 32 + f4] = a3;
}

// ---------------------------------------------------------------------------
// Kz: z[n,h,d] = sum_c We[d, h*64+c] * q[n,h,c].  We staged in smem (padded
// rows of 132 floats for conflict-free strided reads). 384 threads = 1 output
// each per node; persistent blocks loop over nodes.
// ---------------------------------------------------------------------------
__global__ void k_z(const float* __restrict__ We)
{
    extern __shared__ float sm[];
    float* WeS = sm;              // 192 rows x 132 floats
    float* qS  = sm + 192 * 132;  // 128 floats
    const int t = threadIdx.x;    // 384

    const float4* We4 = (const float4*)We;
    for (int i = t; i < 192 * 32; i += 384) {
        int d = i >> 5, c4 = i & 31;
        ((float4*)(WeS + d * 132))[c4] = We4[i];
    }
    __syncthreads();

    const int h = t / 192, d = t % 192;
    const float4* wrow = (const float4*)(WeS + d * 132 + h * 64);

    for (int n = blockIdx.x; n < NN; n += gridDim.x) {
        if (t < 32) ((float4*)qS)[t] = g_q[(size_t)n * 32 + t];
        __syncthreads();
        const float4* qh = (const float4*)(qS + h * 64);
        float acc = 0.f;
        #pragma unroll
        for (int c = 0; c < 16; c++) acc += dot4(wrow[c], qh[c]);
        ((float*)g_z)[(size_t)n * 384 + t] = acc;
        __syncthreads();
    }
}

// ---------------------------------------------------------------------------
// K2: one warp per edge. enc -> logits (q.k + z.attr via shuffle reduces) ->
// w = exp(alpha) (no amax needed: |alpha| < ~3) -> vectorized red.v4 into the
// per-dst aggregates. Single pass over edges; msg read once.
// ---------------------------------------------------------------------------
__global__ void k_edge(const void* __restrict__ ei,
                       const float* __restrict__ tt,
                       const float* __restrict__ lu,
                       const float4* __restrict__ msg4,
                       const float* __restrict__ tw,
                       const float* __restrict__ tb)
{
    __shared__ float encS[8][64];
    const int w = threadIdx.x >> 5, lane = threadIdx.x & 31;
    const size_t e = (size_t)blockIdx.x * 8 + w;
    if (e >= EE) return;

    long long src, dst;
    if (g_is64) {
        const long long* p = (const long long*)ei;
        src = p[e]; dst = p[EE + e];
    } else {
        const int* p = (const int*)ei;
        src = p[e]; dst = p[EE + e];
    }
    const float rel = tt[e] - lu[src];

    float2 twv = ((const float2*)tw)[lane];
    float2 tbv = ((const float2*)tb)[lane];
    float c0 = cosf(rel * twv.x + tbv.x);
    float c1 = cosf(rel * twv.y + tbv.y);
    encS[w][2 * lane]     = c0;
    encS[w][2 * lane + 1] = c1;
    __syncwarp();
    const float4* encF4 = (const float4*)encS[w];

    const size_t mb = e * 32;
    float4 q4 = g_q[(size_t)dst * 32 + lane];
    float4 k4 = g_k[(size_t)src * 32 + lane];
    float4 v4 = g_v[(size_t)src * 32 + lane];
    float4 m4 = msg4[mb + lane];

    // q.k per head (lanes 0..15 hold head0 dims, 16..31 head1)
    float qk = dot4(q4, k4);
    qk += __shfl_xor_sync(0xffffffffu, qk, 8);
    qk += __shfl_xor_sync(0xffffffffu, qk, 4);
    qk += __shfl_xor_sync(0xffffffffu, qk, 2);
    qk += __shfl_xor_sync(0xffffffffu, qk, 1);
    float aqk0 = __shfl_sync(0xffffffffu, qk, 0);
    float aqk1 = __shfl_sync(0xffffffffu, qk, 16);

    // z . attr, attr = [enc(64), msg(128)], z = [2][192]
    const size_t zb0 = (size_t)dst * 96;
    float4 za = g_z[zb0 + lane];
    float4 zb = g_z[zb0 + 32 + lane];
    float4 zc = g_z[zb0 + 64 + lane];
    float4 Aa = (lane < 16) ? encF4[lane]          : msg4[mb + lane - 16];
    float4 Ab = (lane < 16) ? msg4[mb + lane + 16] : encF4[lane - 16];
    float pb = dot4(zb, Ab);
    float p0 = dot4(za, Aa) + ((lane < 16) ? pb : 0.f);
    float p1 = dot4(zc, m4) + ((lane < 16) ? 0.f : pb);
    #pragma unroll
    for (int o = 16; o >= 1; o >>= 1) {
        p0 += __shfl_xor_sync(0xffffffffu, p0, o);
        p1 += __shfl_xor_sync(0xffffffffu, p1, o);
    }

    float w0 = expf(0.125f * (aqk0 + p0));
    float w1 = expf(0.125f * (aqk1 + p1));

    float sc = (lane < 16) ? w0 : w1;
    float4 ev = encF4[lane & 15];
    red4(&g_aggT[(size_t)dst * 32 + lane], sc * ev.x, sc * ev.y, sc * ev.z, sc * ev.w);
    red4(&g_aggV[(size_t)dst * 32 + lane], sc * v4.x, sc * v4.y, sc * v4.z, sc * v4.w);
    red4(&g_aggM[(size_t)dst * 64 + lane],      w0 * m4.x, w0 * m4.y, w0 * m4.z, w0 * m4.w);
    red4(&g_aggM[(size_t)dst * 64 + 32 + lane], w1 * m4.x, w1 * m4.y, w1 * m4.z, w1 * m4.w);
    if (lane == 0) red2(&g_asum[dst], w0, w1);
}

// ---------------------------------------------------------------------------
// K3: out[n,h,c] = skip (already in out) + (aggV[n,h,c] +
//                  sum_d aggE[n,h,d]*We[d,h*64+c]) / (asum[n,h] + 1e-16)
// We in smem (padded 132); 4 nodes per iteration for We-LDS reuse.
// ---------------------------------------------------------------------------
__global__ void k_final(const float* __restrict__ We, float* __restrict__ out)
{
    extern __shared__ float sm[];
    float* WeS = sm;                 // 192 x 132
    float* sA  = sm + 192 * 132;     // 4 x 392  ([h][196] per node)
    float* sS  = sA + 4 * 392;       // 8 asums
    const int t = threadIdx.x;       // 128

    const float4* We4 = (const float4*)We;
    for (int i = t; i < 192 * 32; i += 128) {
        int d = i >> 5, c4 = i & 31;
        ((float4*)(WeS + d * 132))[c4] = We4[i];
    }

    const int j = t, h = t >> 6;
    for (int q0 = blockIdx.x * 4; q0 < NN; q0 += gridDim.x * 4) {
        __syncthreads();
        for (int i = t; i < 4 * 96; i += 128) {
            int ni = i / 96, m = i % 96;
            int node = q0 + ni;
            int hh = m / 48, d4 = m % 48;
            float4 val = (d4 < 16) ? g_aggT[(size_t)node * 32 + hh * 16 + d4]
                                   : g_aggM[(size_t)node * 64 + hh * 32 + (d4 - 16)];
            *(float4*)&sA[ni * 392 + hh * 196 + d4 * 4] = val;
        }
        if (t < 8) sS[t] = ((const float*)g_asum)[(size_t)(q0 + (t >> 1)) * 2 + (t & 1)];
        __syncthreads();

        float acc0 = 0.f, acc1 = 0.f, acc2 = 0.f, acc3 = 0.f;
        const float* a0 = sA + 0 * 392 + h * 196;
        const float* a1 = sA + 1 * 392 + h * 196;
        const float* a2 = sA + 2 * 392 + h * 196;
        const float* a3 = sA + 3 * 392 + h * 196;
        #pragma unroll 4
        for (int d = 0; d < 192; d++) {
            float wv = WeS[d * 132 + j];
            acc0 += wv * a0[d];
            acc1 += wv * a1[d];
            acc2 += wv * a2[d];
            acc3 += wv * a3[d];
        }

        const float* gv = (const float*)g_aggV;
        size_t n0 = (size_t)q0;
        out[(n0 + 0) * 128 + j] += (gv[(n0 + 0) * 128 + j] + acc0) * (1.f / (sS[0 + h] + 1e-16f));
        out[(n0 + 1) * 128 + j] += (gv[(n0 + 1) * 128 + j] + acc1) * (1.f / (sS[2 + h] + 1e-16f));
        out[(n0 + 2) * 128 + j] += (gv[(n0 + 2) * 128 + j] + acc2) * (1.f / (sS[4 + h] + 1e-16f));
        out[(n0 + 3) * 128 + j] += (gv[(n0 + 3) * 128 + j] + acc3) * (1.f / (sS[6 + h] + 1e-16f));
    }
}

// ---------------------------------------------------------------------------
extern "C" void kernel_launch(void* const* d_in, const int* in_sizes, int n_in,
                              void* d_out, int out_size)
{
    const float* x  = (const float*)d_in[0];
    const float* lu = (const float*)d_in[1];
    const float* tt = (const float*)d_in[2];
    const float* msg = (const float*)d_in[3];
    const float* tw = (const float*)d_in[4];
    const float* tb = (const float*)d_in[5];
    const float* Wq = (const float*)d_in[6];
    const float* bq = (const float*)d_in[7];
    const float* Wk = (const float*)d_in[8];
    const float* bk = (const float*)d_in[9];
    const float* Wv = (const float*)d_in[10];
    const float* bv = (const float*)d_in[11];
    const float* We = (const float*)d_in[12];
    const float* Ws = (const float*)d_in[13];
    const float* bs = (const float*)d_in[14];
    const void* ei  = d_in[15];
    float* out = (float*)d_out;

    cudaFuncSetAttribute(k_node,  cudaFuncAttributeMaxDynamicSharedMemorySize, 81920);
    cudaFuncSetAttribute(k_z,     cudaFuncAttributeMaxDynamicSharedMemorySize, 101888);
    cudaFuncSetAttribute(k_final, cudaFuncAttributeMaxDynamicSharedMemorySize, 107680);

    void *pT, *pM, *pV, *pS;
    cudaGetSymbolAddress(&pT, g_aggT);
    cudaGetSymbolAddress(&pM, g_aggM);
    cudaGetSymbolAddress(&pV, g_aggV);
    cudaGetSymbolAddress(&pS, g_asum);
    cudaMemsetAsync(pT, 0, sizeof(g_aggT));
    cudaMemsetAsync(pM, 0, sizeof(g_aggM));
    cudaMemsetAsync(pV, 0, sizeof(g_aggV));
    cudaMemsetAsync(pS, 0, sizeof(g_asum));

    k_detect<<<1, 1>>>((const int*)ei);
    k_node<<<dim3(1563, 4, 1), 256, 81920>>>(x, Wq, bq, Wk, bk, Wv, bv, Ws, bs, (float4*)out);
    k_z<<<592, 384, 101888>>>(We);
    k_edge<<<62500, 256>>>(ei, tt, lu, (const float4*)msg, tw, tb);
    k_final<<<592, 128, 107680>>>(We, out);
}

// round 3
// speedup vs baseline: 1.0325x; 1.0325x over previous
#include <cuda_runtime.h>
#include <math.h>

#define NN 50000
#define EE 500000

// node-space tables (float4 views of [N,128] / [N,2,192])
__device__ __align__(16) float4 g_q[NN * 32];
__device__ __align__(16) float4 g_k[NN * 32];
__device__ __align__(16) float4 g_v[NN * 32];
__device__ __align__(16) float4 g_z[NN * 96];      // [n][2][192] flat [n][384]
// per-dst aggregates (zeroed every launch)
__device__ __align__(16) float4 g_aggT[NN * 32];   // [n][2][64]   sum w*enc
__device__ __align__(16) float4 g_aggM[NN * 64];   // [n][2][128]  sum w*msg
__device__ __align__(16) float4 g_aggV[NN * 32];   // [n][2][64]   sum w*v[src]
__device__ __align__(8)  float2 g_asum[NN];        // [n][2]       sum w
__device__ int g_is64;                             // edge_index dtype flag
// composed weights: z = x @ Zw + bz   (Zw = Wq_h We_h^T per head)
__device__ __align__(16) float g_Zw[128 * 384];
__device__ __align__(16) float g_bz[384];

static __device__ __forceinline__ float dot4(float4 a, float4 b) {
    return a.x * b.x + a.y * b.y + a.z * b.z + a.w * b.w;
}
static __device__ __forceinline__ void red4(float4* p, float x, float y, float z, float w) {
    asm volatile("red.global.add.v4.f32 [%0], {%1,%2,%3,%4};"
                 :: "l"(p), "f"(x), "f"(y), "f"(z), "f"(w) : "memory");
}
static __device__ __forceinline__ void red2(float2* p, float x, float y) {
    asm volatile("red.global.add.v2.f32 [%0], {%1,%2};"
                 :: "l"(p), "f"(x), "f"(y) : "memory");
}

// ---------------------------------------------------------------------------
// K0: detect edge_index dtype (JAX x64-disabled silently yields int32).
// ---------------------------------------------------------------------------
__global__ void k_detect(const int* __restrict__ ei32) {
    int odd_or = 0;
    #pragma unroll
    for (int i = 1; i < 64; i += 2) odd_or |= ei32[i];
    g_is64 = (odd_or == 0) ? 1 : 0;
}

// ---------------------------------------------------------------------------
// Kp: Zw[j, h*192+d] = sum_c Wq[j, h*64+c] * We[d, h*64+c]
//     bz[h*192+d]    = sum_c bq[h*64+c]    * We[d, h*64+c]
// ---------------------------------------------------------------------------
__global__ void k_prep(const float* __restrict__ Wq, const float* __restrict__ bq,
                       const float* __restrict__ We)
{
    int u = blockIdx.x * 256 + threadIdx.x;
    if (u < 128 * 384) {
        int j = u / 384, col = u % 384;
        int h = col / 192, d = col % 192;
        const float4* a = (const float4*)(Wq + j * 128 + h * 64);
        const float4* b = (const float4*)(We + d * 128 + h * 64);
        float acc = 0.f;
        #pragma unroll
        for (int c = 0; c < 16; c++) acc += dot4(a[c], b[c]);
        g_Zw[u] = acc;
    } else if (u < 128 * 384 + 384) {
        int col = u - 128 * 384;
        int h = col / 192, d = col % 192;
        const float4* a = (const float4*)(bq + h * 64);
        const float4* b = (const float4*)(We + d * 128 + h * 64);
        float acc = 0.f;
        #pragma unroll
        for (int c = 0; c < 16; c++) acc += dot4(a[c], b[c]);
        g_bz[col] = acc;
    }
}

// ---------------------------------------------------------------------------
// K1: fused node GEMM, 7 column-slices (q,k,v,skip,z0,z1,z2).
// Tile 64 nodes x 128 cols; 256 threads; 4x8 outputs per thread.
// Per k-step: 4 broadcast scalar LDS (a) + 2 LDS.128 (b) + 32 FMA.
// ---------------------------------------------------------------------------
__global__ void __launch_bounds__(256, 2)
k_gemm(const float* __restrict__ x,
       const float* __restrict__ Wq, const float* __restrict__ bq,
       const float* __restrict__ Wk, const float* __restrict__ bk,
       const float* __restrict__ Wv, const float* __restrict__ bv,
       const float* __restrict__ Ws, const float* __restrict__ bs,
       float* __restrict__ out)
{
    extern __shared__ float sm[];
    float* xs = sm;             // 64 x 132 (padded)
    float* ws = sm + 64 * 132;  // 128 x 128
    const int t = threadIdx.x;
    const int y = blockIdx.y;

    const float* W; const float* B; int RS;
    float* dptr; int ds; int col0 = 0;
    if      (y == 0) { W = Wq; B = bq; RS = 128; dptr = (float*)g_q; ds = 128; }
    else if (y == 1) { W = Wk; B = bk; RS = 128; dptr = (float*)g_k; ds = 128; }
    else if (y == 2) { W = Wv; B = bv; RS = 128; dptr = (float*)g_v; ds = 128; }
    else if (y == 3) { W = Ws; B = bs; RS = 128; dptr = out;         ds = 128; }
    else { col0 = (y - 4) * 128; W = g_Zw + col0; B = g_bz + col0; RS = 384;
           dptr = (float*)g_z; ds = 384; }

    const int m0 = blockIdx.x * 64;
    const float4* x4 = (const float4*)x;
    for (int i = t; i < 64 * 32; i += 256) {
        int m = i >> 5, c4 = i & 31;
        int node = m0 + m;
        float4 v = (node < NN) ? x4[(size_t)node * 32 + c4] : make_float4(0.f, 0.f, 0.f, 0.f);
        *(float4*)&xs[m * 132 + c4 * 4] = v;
    }
    for (int i = t; i < 128 * 32; i += 256) {
        int k = i >> 5, c = (i & 31) * 4;
        *(float4*)&ws[k * 128 + c] = *(const float4*)&W[(size_t)k * RS + c];
    }
    __syncthreads();

    const int tn = t & 15, tm = t >> 4;
    float4 acc[4][2];
    #pragma unroll
    for (int r = 0; r < 4; r++) { acc[r][0] = make_float4(0.f,0.f,0.f,0.f); acc[r][1] = acc[r][0]; }

    const float* xr = xs + tm * 4 * 132;
    const float* wb = ws + tn * 8;

#define FMA4(A, S, Bv) { A.x += (S)*(Bv).x; A.y += (S)*(Bv).y; A.z += (S)*(Bv).z; A.w += (S)*(Bv).w; }
    #pragma unroll 4
    for (int k = 0; k < 128; k++) {
        float4 b0 = *(const float4*)&wb[k * 128];
        float4 b1 = *(const float4*)&wb[k * 128 + 4];
        float a0 = xr[k], a1 = xr[132 + k], a2 = xr[264 + k], a3 = xr[396 + k];
        FMA4(acc[0][0], a0, b0); FMA4(acc[0][1], a0, b1);
        FMA4(acc[1][0], a1, b0); FMA4(acc[1][1], a1, b1);
        FMA4(acc[2][0], a2, b0); FMA4(acc[2][1], a2, b1);
        FMA4(acc[3][0], a3, b0); FMA4(acc[3][1], a3, b1);
    }
#undef FMA4

    float4 bb0 = *(const float4*)&B[tn * 8];
    float4 bb1 = *(const float4*)&B[tn * 8 + 4];
    #pragma unroll
    for (int r = 0; r < 4; r++) {
        int node = m0 + tm * 4 + r;
        if (node >= NN) break;
        float4 o0 = acc[r][0]; o0.x += bb0.x; o0.y += bb0.y; o0.z += bb0.z; o0.w += bb0.w;
        float4 o1 = acc[r][1]; o1.x += bb1.x; o1.y += bb1.y; o1.z += bb1.z; o1.w += bb1.w;
        float* p = dptr + (size_t)node * ds + col0 + tn * 8;
        *(float4*)p = o0;
        *(float4*)(p + 4) = o1;
    }
}

// ---------------------------------------------------------------------------
// K2: one warp per edge. enc -> logits (q.k + z.attr via shuffle reduces) ->
// w = exp(alpha) (no amax needed: |alpha| small) -> red.v4 into aggregates.
// ---------------------------------------------------------------------------
__global__ void k_edge(const void* __restrict__ ei,
                       const float* __restrict__ tt,
                       const float* __restrict__ lu,
                       const float4* __restrict__ msg4,
                       const float* __restrict__ tw,
                       const float* __restrict__ tb)
{
    __shared__ float encS[8][64];
    const int w = threadIdx.x >> 5, lane = threadIdx.x & 31;
    const size_t e = (size_t)blockIdx.x * 8 + w;
    if (e >= EE) return;

    long long src, dst;
    if (g_is64) {
        const long long* p = (const long long*)ei;
        src = p[e]; dst = p[EE + e];
    } else {
        const int* p = (const int*)ei;
        src = p[e]; dst = p[EE + e];
    }
    const float rel = tt[e] - lu[src];

    float2 twv = ((const float2*)tw)[lane];
    float2 tbv = ((const float2*)tb)[lane];
    float c0 = cosf(rel * twv.x + tbv.x);
    float c1 = cosf(rel * twv.y + tbv.y);
    encS[w][2 * lane]     = c0;
    encS[w][2 * lane + 1] = c1;
    __syncwarp();
    const float4* encF4 = (const float4*)encS[w];

    const size_t mb = e * 32;
    float4 q4 = g_q[(size_t)dst * 32 + lane];
    float4 k4 = g_k[(size_t)src * 32 + lane];
    float4 v4 = g_v[(size_t)src * 32 + lane];
    float4 m4 = msg4[mb + lane];

    float qk = dot4(q4, k4);
    qk += __shfl_xor_sync(0xffffffffu, qk, 8);
    qk += __shfl_xor_sync(0xffffffffu, qk, 4);
    qk += __shfl_xor_sync(0xffffffffu, qk, 2);
    qk += __shfl_xor_sync(0xffffffffu, qk, 1);
    float aqk0 = __shfl_sync(0xffffffffu, qk, 0);
    float aqk1 = __shfl_sync(0xffffffffu, qk, 16);

    const size_t zb0 = (size_t)dst * 96;
    float4 za = g_z[zb0 + lane];
    float4 zb = g_z[zb0 + 32 + lane];
    float4 zc = g_z[zb0 + 64 + lane];
    float4 Aa = (lane < 16) ? encF4[lane]          : msg4[mb + lane - 16];
    float4 Ab = (lane < 16) ? msg4[mb + lane + 16] : encF4[lane - 16];
    float pb = dot4(zb, Ab);
    float p0 = dot4(za, Aa) + ((lane < 16) ? pb : 0.f);
    float p1 = dot4(zc, m4) + ((lane < 16) ? 0.f : pb);
    #pragma unroll
    for (int o = 16; o >= 1; o >>= 1) {
        p0 += __shfl_xor_sync(0xffffffffu, p0, o);
        p1 += __shfl_xor_sync(0xffffffffu, p1, o);
    }

    float w0 = expf(0.125f * (aqk0 + p0));
    float w1 = expf(0.125f * (aqk1 + p1));

    float sc = (lane < 16) ? w0 : w1;
    float4 ev = encF4[lane & 15];
    red4(&g_aggT[(size_t)dst * 32 + lane], sc * ev.x, sc * ev.y, sc * ev.z, sc * ev.w);
    red4(&g_aggV[(size_t)dst * 32 + lane], sc * v4.x, sc * v4.y, sc * v4.z, sc * v4.w);
    red4(&g_aggM[(size_t)dst * 64 + lane],      w0 * m4.x, w0 * m4.y, w0 * m4.z, w0 * m4.w);
    red4(&g_aggM[(size_t)dst * 64 + 32 + lane], w1 * m4.x, w1 * m4.y, w1 * m4.z, w1 * m4.w);
    if (lane == 0) red2(&g_asum[dst], w0, w1);
}

// ---------------------------------------------------------------------------
// K3: out[n,h,c] += (aggV[n,h,c] + sum_d aggE[n,h,d]*We[d,h*64+c]) / asum[n,h]
// ---------------------------------------------------------------------------
__global__ void k_final(const float* __restrict__ We, float* __restrict__ out)
{
    extern __shared__ float sm[];
    float* WeS = sm;                 // 192 x 132
    float* sA  = sm + 192 * 132;     // 4 x 392
    float* sS  = sA + 4 * 392;       // 8 asums
    const int t = threadIdx.x;       // 128

    const float4* We4 = (const float4*)We;
    for (int i = t; i < 192 * 32; i += 128) {
        int d = i >> 5, c4 = i & 31;
        ((float4*)(WeS + d * 132))[c4] = We4[i];
    }

    const int j = t, h = t >> 6;
    for (int q0 = blockIdx.x * 4; q0 < NN; q0 += gridDim.x * 4) {
        __syncthreads();
        for (int i = t; i < 4 * 96; i += 128) {
            int ni = i / 96, m = i % 96;
            int node = q0 + ni;
            int hh = m / 48, d4 = m % 48;
            float4 val = (d4 < 16) ? g_aggT[(size_t)node * 32 + hh * 16 + d4]
                                   : g_aggM[(size_t)node * 64 + hh * 32 + (d4 - 16)];
            *(float4*)&sA[ni * 392 + hh * 196 + d4 * 4] = val;
        }
        if (t < 8) sS[t] = ((const float*)g_asum)[(size_t)(q0 + (t >> 1)) * 2 + (t & 1)];
        __syncthreads();

        float acc0 = 0.f, acc1 = 0.f, acc2 = 0.f, acc3 = 0.f;
        const float* a0 = sA + 0 * 392 + h * 196;
        const float* a1 = sA + 1 * 392 + h * 196;
        const float* a2 = sA + 2 * 392 + h * 196;
        const float* a3 = sA + 3 * 392 + h * 196;
        #pragma unroll 4
        for (int d = 0; d < 192; d++) {
            float wv = WeS[d * 132 + j];
            acc0 += wv * a0[d];
            acc1 += wv * a1[d];
            acc2 += wv * a2[d];
            acc3 += wv * a3[d];
        }

        const float* gv = (const float*)g_aggV;
        size_t n0 = (size_t)q0;
        out[(n0 + 0) * 128 + j] += (gv[(n0 + 0) * 128 + j] + acc0) * (1.f / (sS[0 + h] + 1e-16f));
        out[(n0 + 1) * 128 + j] += (gv[(n0 + 1) * 128 + j] + acc1) * (1.f / (sS[2 + h] + 1e-16f));
        out[(n0 + 2) * 128 + j] += (gv[(n0 + 2) * 128 + j] + acc2) * (1.f / (sS[4 + h] + 1e-16f));
        out[(n0 + 3) * 128 + j] += (gv[(n0 + 3) * 128 + j] + acc3) * (1.f / (sS[6 + h] + 1e-16f));
    }
}

// ---------------------------------------------------------------------------
extern "C" void kernel_launch(void* const* d_in, const int* in_sizes, int n_in,
                              void* d_out, int out_size)
{
    const float* x  = (const float*)d_in[0];
    const float* lu = (const float*)d_in[1];
    const float* tt = (const float*)d_in[2];
    const float* msg = (const float*)d_in[3];
    const float* tw = (const float*)d_in[4];
    const float* tb = (const float*)d_in[5];
    const float* Wq = (const float*)d_in[6];
    const float* bq = (const float*)d_in[7];
    const float* Wk = (const float*)d_in[8];
    const float* bk = (const float*)d_in[9];
    const float* Wv = (const float*)d_in[10];
    const float* bv = (const float*)d_in[11];
    const float* We = (const float*)d_in[12];
    const float* Ws = (const float*)d_in[13];
    const float* bs = (const float*)d_in[14];
    const void* ei  = d_in[15];
    float* out = (float*)d_out;

    cudaFuncSetAttribute(k_gemm,  cudaFuncAttributeMaxDynamicSharedMemorySize, 99328);
    cudaFuncSetAttribute(k_final, cudaFuncAttributeMaxDynamicSharedMemorySize, 107680);

    void *pT, *pM, *pV, *pS;
    cudaGetSymbolAddress(&pT, g_aggT);
    cudaGetSymbolAddress(&pM, g_aggM);
    cudaGetSymbolAddress(&pV, g_aggV);
    cudaGetSymbolAddress(&pS, g_asum);
    cudaMemsetAsync(pT, 0, sizeof(g_aggT));
    cudaMemsetAsync(pM, 0, sizeof(g_aggM));
    cudaMemsetAsync(pV, 0, sizeof(g_aggV));
    cudaMemsetAsync(pS, 0, sizeof(g_asum));

    k_detect<<<1, 1>>>((const int*)ei);
    k_prep<<<194, 256>>>(Wq, bq, We);
    k_gemm<<<dim3(782, 7, 1), 256, 99328>>>(x, Wq, bq, Wk, bk, Wv, bv, Ws, bs, out);
    k_edge<<<62500, 256>>>(ei, tt, lu, (const float4*)msg, tw, tb);
    k_final<<<592, 128, 107680>>>(We, out);
}

// round 4
// speedup vs baseline: 1.1583x; 1.1218x over previous
#include <cuda_runtime.h>
#include <math.h>

#define NN 50000
#define EE 500000

// node-space tables (float4 views of [N,128] / [N,2,192])
__device__ __align__(16) float4 g_q[NN * 32];
__device__ __align__(16) float4 g_k[NN * 32];
__device__ __align__(16) float4 g_v[NN * 32];
__device__ __align__(16) float4 g_z[NN * 96];      // [n][2][192] flat [n][384]
// per-dst aggregates (written once by k_edge2, no memset needed)
__device__ __align__(16) float4 g_aggT[NN * 32];   // [n][2][64]   sum w*enc
__device__ __align__(16) float4 g_aggM[NN * 64];   // [n][2][128]  sum w*msg
__device__ __align__(16) float4 g_aggV[NN * 32];   // [n][2][64]   sum w*v[src]
__device__ __align__(8)  float2 g_asum[NN];        // [n][2]       sum w
__device__ int g_is64;                             // edge_index dtype flag
// composed weights: z = x @ Zw + bz
__device__ __align__(16) float g_Zw[128 * 384];
__device__ __align__(16) float g_bz[384];
// counting-sort scratch
__device__ int g_cnt[NN];
__device__ int g_offA[NN];
__device__ int g_bsum[128];
__device__ int g_bpre[128];
__device__ int g_off[NN + 1];
__device__ int g_pos[NN];
__device__ int g_eid[EE];

static __device__ __forceinline__ float dot4(float4 a, float4 b) {
    return a.x * b.x + a.y * b.y + a.z * b.z + a.w * b.w;
}

// ---------------------------------------------------------------------------
// K0: detect edge_index dtype (JAX x64-disabled silently yields int32).
// ---------------------------------------------------------------------------
__global__ void k_detect(const int* __restrict__ ei32) {
    int odd_or = 0;
    #pragma unroll
    for (int i = 1; i < 64; i += 2) odd_or |= ei32[i];
    g_is64 = (odd_or == 0) ? 1 : 0;
}

// ---------------------------------------------------------------------------
// Kp: Zw[j, h*192+d] = sum_c Wq[j, h*64+c] * We[d, h*64+c];  bz likewise.
// ---------------------------------------------------------------------------
__global__ void k_prep(const float* __restrict__ Wq, const float* __restrict__ bq,
                       const float* __restrict__ We)
{
    int u = blockIdx.x * 256 + threadIdx.x;
    if (u < 128 * 384) {
        int j = u / 384, col = u % 384;
        int h = col / 192, d = col % 192;
        const float4* a = (const float4*)(Wq + j * 128 + h * 64);
        const float4* b = (const float4*)(We + d * 128 + h * 64);
        float acc = 0.f;
        #pragma unroll
        for (int c = 0; c < 16; c++) acc += dot4(a[c], b[c]);
        g_Zw[u] = acc;
    } else if (u < 128 * 384 + 384) {
        int col = u - 128 * 384;
        int h = col / 192, d = col % 192;
        const float4* a = (const float4*)(bq + h * 64);
        const float4* b = (const float4*)(We + d * 128 + h * 64);
        float acc = 0.f;
        #pragma unroll
        for (int c = 0; c < 16; c++) acc += dot4(a[c], b[c]);
        g_bz[col] = acc;
    }
}

// ---------------------------------------------------------------------------
// K1: fused node GEMM, 7 column-slices (q,k,v,skip,z0,z1,z2).
// ---------------------------------------------------------------------------
__global__ void __launch_bounds__(256, 2)
k_gemm(const float* __restrict__ x,
       const float* __restrict__ Wq, const float* __restrict__ bq,
       const float* __restrict__ Wk, const float* __restrict__ bk,
       const float* __restrict__ Wv, const float* __restrict__ bv,
       const float* __restrict__ Ws, const float* __restrict__ bs,
       float* __restrict__ out)
{
    extern __shared__ float sm[];
    float* xs = sm;             // 64 x 132 (padded)
    float* ws = sm + 64 * 132;  // 128 x 128
    const int t = threadIdx.x;
    const int y = blockIdx.y;

    const float* W; const float* B; int RS;
    float* dptr; int ds; int col0 = 0;
    if      (y == 0) { W = Wq; B = bq; RS = 128; dptr = (float*)g_q; ds = 128; }
    else if (y == 1) { W = Wk; B = bk; RS = 128; dptr = (float*)g_k; ds = 128; }
    else if (y == 2) { W = Wv; B = bv; RS = 128; dptr = (float*)g_v; ds = 128; }
    else if (y == 3) { W = Ws; B = bs; RS = 128; dptr = out;         ds = 128; }
    else { col0 = (y - 4) * 128; W = g_Zw + col0; B = g_bz + col0; RS = 384;
           dptr = (float*)g_z; ds = 384; }

    const int m0 = blockIdx.x * 64;
    const float4* x4 = (const float4*)x;
    for (int i = t; i < 64 * 32; i += 256) {
        int m = i >> 5, c4 = i & 31;
        int node = m0 + m;
        float4 v = (node < NN) ? x4[(size_t)node * 32 + c4] : make_float4(0.f, 0.f, 0.f, 0.f);
        *(float4*)&xs[m * 132 + c4 * 4] = v;
    }
    for (int i = t; i < 128 * 32; i += 256) {
        int k = i >> 5, c = (i & 31) * 4;
        *(float4*)&ws[k * 128 + c] = *(const float4*)&W[(size_t)k * RS + c];
    }
    __syncthreads();

    const int tn = t & 15, tm = t >> 4;
    float4 acc[4][2];
    #pragma unroll
    for (int r = 0; r < 4; r++) { acc[r][0] = make_float4(0.f,0.f,0.f,0.f); acc[r][1] = acc[r][0]; }

    const float* xr = xs + tm * 4 * 132;
    const float* wb = ws + tn * 8;

#define FMA4(A, S, Bv) { A.x += (S)*(Bv).x; A.y += (S)*(Bv).y; A.z += (S)*(Bv).z; A.w += (S)*(Bv).w; }
    #pragma unroll 4
    for (int k = 0; k < 128; k++) {
        float4 b0 = *(const float4*)&wb[k * 128];
        float4 b1 = *(const float4*)&wb[k * 128 + 4];
        float a0 = xr[k], a1 = xr[132 + k], a2 = xr[264 + k], a3 = xr[396 + k];
        FMA4(acc[0][0], a0, b0); FMA4(acc[0][1], a0, b1);
        FMA4(acc[1][0], a1, b0); FMA4(acc[1][1], a1, b1);
        FMA4(acc[2][0], a2, b0); FMA4(acc[2][1], a2, b1);
        FMA4(acc[3][0], a3, b0); FMA4(acc[3][1], a3, b1);
    }
#undef FMA4

    float4 bb0 = *(const float4*)&B[tn * 8];
    float4 bb1 = *(const float4*)&B[tn * 8 + 4];
    #pragma unroll
    for (int r = 0; r < 4; r++) {
        int node = m0 + tm * 4 + r;
        if (node >= NN) break;
        float4 o0 = acc[r][0]; o0.x += bb0.x; o0.y += bb0.y; o0.z += bb0.z; o0.w += bb0.w;
        float4 o1 = acc[r][1]; o1.x += bb1.x; o1.y += bb1.y; o1.z += bb1.z; o1.w += bb1.w;
        float* p = dptr + (size_t)node * ds + col0 + tn * 8;
        *(float4*)p = o0;
        *(float4*)(p + 4) = o1;
    }
}

// ---------------------------------------------------------------------------
// Counting sort of edges by dst: hist -> 2-level scan -> scatter.
// ---------------------------------------------------------------------------
__global__ void k_hist(const void* __restrict__ ei) {
    const int e = blockIdx.x * 256 + threadIdx.x;
    if (e >= EE) return;
    int dst = g_is64 ? (int)((const long long*)ei)[EE + e] : ((const int*)ei)[EE + e];
    atomicAdd(&g_cnt[dst], 1);
}

__global__ void k_scanA() {
    __shared__ int s[512];
    const int tid = threadIdx.x;
    const int i = blockIdx.x * 512 + tid;
    int c = (i < NN) ? g_cnt[i] : 0;
    s[tid] = c;
    __syncthreads();
    #pragma unroll
    for (int o = 1; o < 512; o <<= 1) {
        int v = (tid >= o) ? s[tid - o] : 0;
        __syncthreads();
        if (tid >= o) s[tid] += v;
        __syncthreads();
    }
    if (i < NN) g_offA[i] = s[tid] - c;        // exclusive within chunk
    if (tid == 511) g_bsum[blockIdx.x] = s[511];
}

__global__ void k_scanB(int nchunks) {
    if (threadIdx.x == 0) {
        int run = 0;
        for (int b = 0; b < nchunks; b++) { g_bpre[b] = run; run += g_bsum[b]; }
        g_off[NN] = EE;
    }
}

__global__ void k_scanC() {
    const int i = blockIdx.x * 512 + threadIdx.x;
    if (i < NN) {
        int v = g_offA[i] + g_bpre[blockIdx.x];
        g_off[i] = v;
        g_pos[i] = v;
    }
}

__global__ void k_scatter(const void* __restrict__ ei) {
    const int e = blockIdx.x * 256 + threadIdx.x;
    if (e >= EE) return;
    int dst = g_is64 ? (int)((const long long*)ei)[EE + e] : ((const int*)ei)[EE + e];
    int p = atomicAdd(&g_pos[dst], 1);
    g_eid[p] = e;
}

// ---------------------------------------------------------------------------
// K2: one warp per dst segment. q/z/time-weights in registers once per node;
// serial loop over the segment's edges; register accumulation; single write.
// No atomics, no memsets.
// ---------------------------------------------------------------------------
__global__ void __launch_bounds__(256)
k_edge2(const void* __restrict__ ei,
        const float* __restrict__ tt,
        const float* __restrict__ lu,
        const float4* __restrict__ msg4,
        const float* __restrict__ tw,
        const float* __restrict__ tb)
{
    const int w = threadIdx.x >> 5, lane = threadIdx.x & 31;
    const int dst = blockIdx.x * 8 + w;
    if (dst >= NN) return;
    const int is64 = g_is64;
    const int beg = g_off[dst], end = g_off[dst + 1];

    const int lq = lane & 15;
    const float4 tw4 = ((const float4*)tw)[lq];
    const float4 tb4 = ((const float4*)tb)[lq];
    const float4 q4 = g_q[(size_t)dst * 32 + lane];
    const size_t zb0 = (size_t)dst * 96;
    const float4 za = g_z[zb0 + lane];
    const float4 zb = g_z[zb0 + 32 + lane];
    const float4 zc = g_z[zb0 + 64 + lane];

    float4 aT = make_float4(0.f, 0.f, 0.f, 0.f), aV = aT, aM0 = aT, aM1 = aT;
    float s0 = 0.f, s1 = 0.f;

    for (int p = beg; p < end; p++) {
        const int eid = g_eid[p];
        long long src = is64 ? ((const long long*)ei)[eid]
                             : (long long)((const int*)ei)[eid];
        const float rel = tt[eid] - lu[src];

        float4 ev;
        ev.x = __cosf(rel * tw4.x + tb4.x);
        ev.y = __cosf(rel * tw4.y + tb4.y);
        ev.z = __cosf(rel * tw4.z + tb4.z);
        ev.w = __cosf(rel * tw4.w + tb4.w);

        const size_t mb = (size_t)eid * 32;
        float4 k4 = g_k[(size_t)src * 32 + lane];
        float4 v4 = g_v[(size_t)src * 32 + lane];
        float4 m4 = msg4[mb + lane];

        // q.k per head (lanes 0..15 head0, 16..31 head1)
        float qk = dot4(q4, k4);
        qk += __shfl_xor_sync(0xffffffffu, qk, 8);
        qk += __shfl_xor_sync(0xffffffffu, qk, 4);
        qk += __shfl_xor_sync(0xffffffffu, qk, 2);
        qk += __shfl_xor_sync(0xffffffffu, qk, 1);
        float aqk0 = __shfl_sync(0xffffffffu, qk, 0);
        float aqk1 = __shfl_sync(0xffffffffu, qk, 16);

        // z . attr, attr = [enc(64), msg(128)]
        float4 Aa = (lane < 16) ? ev : msg4[mb + lane - 16];
        float4 Ab = (lane < 16) ? msg4[mb + lane + 16] : ev;
        float pb = dot4(zb, Ab);
        float p0 = dot4(za, Aa) + ((lane < 16) ? pb : 0.f);
        float p1 = dot4(zc, m4) + ((lane < 16) ? 0.f : pb);
        #pragma unroll
        for (int o = 16; o >= 1; o >>= 1) {
            p0 += __shfl_xor_sync(0xffffffffu, p0, o);
            p1 += __shfl_xor_sync(0xffffffffu, p1, o);
        }

        float w0 = __expf(0.125f * (aqk0 + p0));
        float w1 = __expf(0.125f * (aqk1 + p1));

        float sc = (lane < 16) ? w0 : w1;
        aT.x += sc * ev.x; aT.y += sc * ev.y; aT.z += sc * ev.z; aT.w += sc * ev.w;
        aV.x += sc * v4.x; aV.y += sc * v4.y; aV.z += sc * v4.z; aV.w += sc * v4.w;
        aM0.x += w0 * m4.x; aM0.y += w0 * m4.y; aM0.z += w0 * m4.z; aM0.w += w0 * m4.w;
        aM1.x += w1 * m4.x; aM1.y += w1 * m4.y; aM1.z += w1 * m4.z; aM1.w += w1 * m4.w;
        s0 += w0; s1 += w1;
    }

    g_aggT[(size_t)dst * 32 + lane] = aT;
    g_aggV[(size_t)dst * 32 + lane] = aV;
    g_aggM[(size_t)dst * 64 + lane]      = aM0;
    g_aggM[(size_t)dst * 64 + 32 + lane] = aM1;
    if (lane == 0) g_asum[dst] = make_float2(s0, s1);
}

// ---------------------------------------------------------------------------
// K3: out[n,h,c] += (aggV[n,h,c] + sum_d aggE[n,h,d]*We[d,h*64+c]) / asum[n,h]
// ---------------------------------------------------------------------------
__global__ void k_final(const float* __restrict__ We, float* __restrict__ out)
{
    extern __shared__ float sm[];
    float* WeS = sm;                 // 192 x 132
    float* sA  = sm + 192 * 132;     // 4 x 392
    float* sS  = sA + 4 * 392;       // 8 asums
    const int t = threadIdx.x;       // 128

    const float4* We4 = (const float4*)We;
    for (int i = t; i < 192 * 32; i += 128) {
        int d = i >> 5, c4 = i & 31;
        ((float4*)(WeS + d * 132))[c4] = We4[i];
    }

    const int j = t, h = t >> 6;
    for (int q0 = blockIdx.x * 4; q0 < NN; q0 += gridDim.x * 4) {
        __syncthreads();
        for (int i = t; i < 4 * 96; i += 128) {
            int ni = i / 96, m = i % 96;
            int node = q0 + ni;
            int hh = m / 48, d4 = m % 48;
            float4 val = (d4 < 16) ? g_aggT[(size_t)node * 32 + hh * 16 + d4]
                                   : g_aggM[(size_t)node * 64 + hh * 32 + (d4 - 16)];
            *(float4*)&sA[ni * 392 + hh * 196 + d4 * 4] = val;
        }
        if (t < 8) sS[t] = ((const float*)g_asum)[(size_t)(q0 + (t >> 1)) * 2 + (t & 1)];
        __syncthreads();

        float acc0 = 0.f, acc1 = 0.f, acc2 = 0.f, acc3 = 0.f;
        const float* a0 = sA + 0 * 392 + h * 196;
        const float* a1 = sA + 1 * 392 + h * 196;
        const float* a2 = sA + 2 * 392 + h * 196;
        const float* a3 = sA + 3 * 392 + h * 196;
        #pragma unroll 4
        for (int d = 0; d < 192; d++) {
            float wv = WeS[d * 132 + j];
            acc0 += wv * a0[d];
            acc1 += wv * a1[d];
            acc2 += wv * a2[d];
            acc3 += wv * a3[d];
        }

        const float* gv = (const float*)g_aggV;
        size_t n0 = (size_t)q0;
        out[(n0 + 0) * 128 + j] += (gv[(n0 + 0) * 128 + j] + acc0) * (1.f / (sS[0 + h] + 1e-16f));
        out[(n0 + 1) * 128 + j] += (gv[(n0 + 1) * 128 + j] + acc1) * (1.f / (sS[2 + h] + 1e-16f));
        out[(n0 + 2) * 128 + j] += (gv[(n0 + 2) * 128 + j] + acc2) * (1.f / (sS[4 + h] + 1e-16f));
        out[(n0 + 3) * 128 + j] += (gv[(n0 + 3) * 128 + j] + acc3) * (1.f / (sS[6 + h] + 1e-16f));
    }
}

// ---------------------------------------------------------------------------
extern "C" void kernel_launch(void* const* d_in, const int* in_sizes, int n_in,
                              void* d_out, int out_size)
{
    const float* x  = (const float*)d_in[0];
    const float* lu = (const float*)d_in[1];
    const float* tt = (const float*)d_in[2];
    const float* msg = (const float*)d_in[3];
    const float* tw = (const float*)d_in[4];
    const float* tb = (const float*)d_in[5];
    const float* Wq = (const float*)d_in[6];
    const float* bq = (const float*)d_in[7];
    const float* Wk = (const float*)d_in[8];
    const float* bk = (const float*)d_in[9];
    const float* Wv = (const float*)d_in[10];
    const float* bv = (const float*)d_in[11];
    const float* We = (const float*)d_in[12];
    const float* Ws = (const float*)d_in[13];
    const float* bs = (const float*)d_in[14];
    const void* ei  = d_in[15];
    float* out = (float*)d_out;

    cudaFuncSetAttribute(k_gemm,  cudaFuncAttributeMaxDynamicSharedMemorySize, 99328);
    cudaFuncSetAttribute(k_final, cudaFuncAttributeMaxDynamicSharedMemorySize, 107680);

    void* pcnt;
    cudaGetSymbolAddress(&pcnt, g_cnt);
    cudaMemsetAsync(pcnt, 0, NN * sizeof(int));

    const int NCHUNK = (NN + 511) / 512;   // 98

    k_detect<<<1, 1>>>((const int*)ei);
    k_prep<<<194, 256>>>(Wq, bq, We);
    k_gemm<<<dim3(782, 7, 1), 256, 99328>>>(x, Wq, bq, Wk, bk, Wv, bv, Ws, bs, out);
    k_hist<<<(EE + 255) / 256, 256>>>(ei);
    k_scanA<<<NCHUNK, 512>>>();
    k_scanB<<<1, 32>>>(NCHUNK);
    k_scanC<<<NCHUNK, 512>>>();
    k_scatter<<<(EE + 255) / 256, 256>>>(ei);
    k_edge2<<<(NN + 7) / 8, 256>>>(ei, tt, lu, (const float4*)msg, tw, tb);
    k_final<<<592, 128, 107680>>>(We, out);
}

// round 5
// speedup vs baseline: 1.4298x; 1.2344x over previous
#include <cuda_runtime.h>
#include <math.h>

#define NN 50000
#define EE 500000

// node-space tables
__device__ __align__(16) float4 g_q[NN * 32];
__device__ __align__(16) float4 g_k[NN * 32];
__device__ __align__(16) float4 g_v[NN * 32];
__device__ __align__(16) float4 g_z[NN * 96];      // [n][2][192] flat [n][384]
// per-dst aggregates (written once by k_edge2)
__device__ __align__(16) float4 g_aggT[NN * 32];   // [n][2][64]   sum w*enc
__device__ __align__(16) float4 g_aggM[NN * 64];   // [n][2][128]  sum w*msg
__device__ __align__(16) float4 g_aggV[NN * 32];   // [n][2][64]   sum w*v[src]
__device__ __align__(8)  float2 g_asum[NN];        // [n][2]       sum w
__device__ int g_is64;
// combined weights: cols [q(0) k(128) v(256) skip(384) z(512..895)]
__device__ __align__(16) float g_Wall[128 * 896];
__device__ __align__(16) float g_ball[896];
// counting-sort scratch
__device__ int g_cnt[NN];
__device__ int g_offA[NN];
__device__ int g_bsum[128];
__device__ int g_bpre[128];
__device__ int g_off[NN + 1];
__device__ int g_pos[NN];
__device__ int g_eid[EE];

static __device__ __forceinline__ float dot4(float4 a, float4 b) {
    return a.x * b.x + a.y * b.y + a.z * b.z + a.w * b.w;
}

// ---------------------------------------------------------------------------
__global__ void k_detect(const int* __restrict__ ei32) {
    int odd_or = 0;
    #pragma unroll
    for (int i = 1; i < 64; i += 2) odd_or |= ei32[i];
    g_is64 = (odd_or == 0) ? 1 : 0;
}

// ---------------------------------------------------------------------------
// Kp: build combined weight matrix [128][896] + bias [896].
// cols 0..511: copy Wq,Wk,Wv,Ws. cols 512..895: Zw[j,h*192+d]=sum_c Wq[j,hc]We[d,hc]
// ---------------------------------------------------------------------------
__global__ void k_prep(const float* __restrict__ Wq, const float* __restrict__ bq,
                       const float* __restrict__ Wk, const float* __restrict__ bk,
                       const float* __restrict__ Wv, const float* __restrict__ bv,
                       const float* __restrict__ Ws, const float* __restrict__ bs,
                       const float* __restrict__ We)
{
    int u = blockIdx.x * 256 + threadIdx.x;
    if (u < 128 * 512) {
        int j = u >> 9, c = u & 511;
        const float* src = (c < 128) ? Wq : (c < 256) ? Wk : (c < 384) ? Wv : Ws;
        g_Wall[j * 896 + c] = src[j * 128 + (c & 127)];
    } else if (u < 128 * 896) {
        int v = u - 128 * 512;
        int j = v / 384, col = v % 384;
        int h = col / 192, d = col % 192;
        const float4* a = (const float4*)(Wq + j * 128 + h * 64);
        const float4* b = (const float4*)(We + d * 128 + h * 64);
        float acc = 0.f;
        #pragma unroll
        for (int c = 0; c < 16; c++) acc += dot4(a[c], b[c]);
        g_Wall[j * 896 + 512 + col] = acc;
    } else if (u < 128 * 896 + 896) {
        int c = u - 128 * 896;
        if (c < 512) {
            const float* src = (c < 128) ? bq : (c < 256) ? bk : (c < 384) ? bv : bs;
            g_ball[c] = src[c & 127];
        } else {
            int col = c - 512;
            int h = col / 192, d = col % 192;
            const float4* a = (const float4*)(bq + h * 64);
            const float4* b = (const float4*)(We + d * 128 + h * 64);
            float acc = 0.f;
            #pragma unroll
            for (int cc = 0; cc < 16; cc++) acc += dot4(a[cc], b[cc]);
            g_ball[c] = acc;
        }
    }
}

// ---------------------------------------------------------------------------
// K1: node GEMM [50000,128] @ [128,896]. Tile 128x128, 8x8 per thread,
// k-panels of 32 with x transposed into smem (all LDS are .128).
// ---------------------------------------------------------------------------
__global__ void __launch_bounds__(256, 2)
k_gemm(const float* __restrict__ x, float* __restrict__ out)
{
    __shared__ float xs[32][132];   // [k][m] transposed x panel
    __shared__ float ws[32][128];   // [k][n]
    const int t = threadIdx.x;
    const int y = blockIdx.y;
    const int col0 = y * 128;

    float* dptr; int ds; int dcol0 = 0;
    if      (y == 0) { dptr = (float*)g_q; ds = 128; }
    else if (y == 1) { dptr = (float*)g_k; ds = 128; }
    else if (y == 2) { dptr = (float*)g_v; ds = 128; }
    else if (y == 3) { dptr = out;         ds = 128; }
    else { dptr = (float*)g_z; ds = 384; dcol0 = (y - 4) * 128; }

    const int m0 = blockIdx.x * 128;
    const float4* x4 = (const float4*)x;
    const int tn = t & 15, tm = t >> 4;

    float4 acc[8][2];
    #pragma unroll
    for (int r = 0; r < 8; r++) { acc[r][0] = make_float4(0.f,0.f,0.f,0.f); acc[r][1] = acc[r][0]; }

#define FMA4(A, S, Bv) { A.x += (S)*(Bv).x; A.y += (S)*(Bv).y; A.z += (S)*(Bv).z; A.w += (S)*(Bv).w; }
    for (int k0 = 0; k0 < 128; k0 += 32) {
        // x panel: 128 rows x 32 k, transposed store
        #pragma unroll
        for (int i = t; i < 1024; i += 256) {
            int m = i >> 3, c4 = i & 7;
            int node = m0 + m;
            float4 v = (node < NN) ? x4[(size_t)node * 32 + (k0 >> 2) + c4]
                                   : make_float4(0.f, 0.f, 0.f, 0.f);
            int kk = c4 * 4;
            xs[kk + 0][m] = v.x; xs[kk + 1][m] = v.y;
            xs[kk + 2][m] = v.z; xs[kk + 3][m] = v.w;
        }
        // w panel: 32 k x 128 cols
        #pragma unroll
        for (int i = t; i < 1024; i += 256) {
            int kk = i >> 5, c4 = i & 31;
            *(float4*)&ws[kk][c4 * 4] = *(const float4*)&g_Wall[(size_t)(k0 + kk) * 896 + col0 + c4 * 4];
        }
        __syncthreads();

        #pragma unroll
        for (int kk = 0; kk < 32; kk++) {
            float4 a0 = *(const float4*)&xs[kk][tm * 8];
            float4 a1 = *(const float4*)&xs[kk][tm * 8 + 4];
            float4 b0 = *(const float4*)&ws[kk][tn * 8];
            float4 b1 = *(const float4*)&ws[kk][tn * 8 + 4];
            FMA4(acc[0][0], a0.x, b0); FMA4(acc[0][1], a0.x, b1);
            FMA4(acc[1][0], a0.y, b0); FMA4(acc[1][1], a0.y, b1);
            FMA4(acc[2][0], a0.z, b0); FMA4(acc[2][1], a0.z, b1);
            FMA4(acc[3][0], a0.w, b0); FMA4(acc[3][1], a0.w, b1);
            FMA4(acc[4][0], a1.x, b0); FMA4(acc[4][1], a1.x, b1);
            FMA4(acc[5][0], a1.y, b0); FMA4(acc[5][1], a1.y, b1);
            FMA4(acc[6][0], a1.z, b0); FMA4(acc[6][1], a1.z, b1);
            FMA4(acc[7][0], a1.w, b0); FMA4(acc[7][1], a1.w, b1);
        }
        __syncthreads();
    }
#undef FMA4

    float4 bb0 = *(const float4*)&g_ball[col0 + tn * 8];
    float4 bb1 = *(const float4*)&g_ball[col0 + tn * 8 + 4];
    #pragma unroll
    for (int r = 0; r < 8; r++) {
        int node = m0 + tm * 8 + r;
        if (node >= NN) break;
        float4 o0 = acc[r][0]; o0.x += bb0.x; o0.y += bb0.y; o0.z += bb0.z; o0.w += bb0.w;
        float4 o1 = acc[r][1]; o1.x += bb1.x; o1.y += bb1.y; o1.z += bb1.z; o1.w += bb1.w;
        float* p = dptr + (size_t)node * ds + dcol0 + tn * 8;
        *(float4*)p = o0;
        *(float4*)(p + 4) = o1;
    }
}

// ---------------------------------------------------------------------------
// Counting sort by dst
// ---------------------------------------------------------------------------
__global__ void k_hist(const void* __restrict__ ei) {
    const int e = blockIdx.x * 256 + threadIdx.x;
    if (e >= EE) return;
    int dst = g_is64 ? (int)((const long long*)ei)[EE + e] : ((const int*)ei)[EE + e];
    atomicAdd(&g_cnt[dst], 1);
}

__global__ void k_scanA() {
    __shared__ int s[512];
    const int tid = threadIdx.x;
    const int i = blockIdx.x * 512 + tid;
    int c = (i < NN) ? g_cnt[i] : 0;
    s[tid] = c;
    __syncthreads();
    #pragma unroll
    for (int o = 1; o < 512; o <<= 1) {
        int v = (tid >= o) ? s[tid - o] : 0;
        __syncthreads();
        if (tid >= o) s[tid] += v;
        __syncthreads();
    }
    if (i < NN) g_offA[i] = s[tid] - c;
    if (tid == 511) g_bsum[blockIdx.x] = s[511];
}

__global__ void k_scanB(int nchunks) {
    if (threadIdx.x == 0) {
        int run = 0;
        for (int b = 0; b < nchunks; b++) { g_bpre[b] = run; run += g_bsum[b]; }
        g_off[NN] = EE;
    }
}

__global__ void k_scanC() {
    const int i = blockIdx.x * 512 + threadIdx.x;
    if (i < NN) {
        int v = g_offA[i] + g_bpre[blockIdx.x];
        g_off[i] = v;
        g_pos[i] = v;
    }
}

__global__ void k_scatter(const void* __restrict__ ei) {
    const int e = blockIdx.x * 256 + threadIdx.x;
    if (e >= EE) return;
    int dst = g_is64 ? (int)((const long long*)ei)[EE + e] : ((const int*)ei)[EE + e];
    int p = atomicAdd(&g_pos[dst], 1);
    g_eid[p] = e;
}

// ---------------------------------------------------------------------------
// K2: warp per dst segment, lane-batched edge prefetch (MLP=32), register
// accumulation, single write. qk partials folded into the z.attr reduction.
// ---------------------------------------------------------------------------
__global__ void __launch_bounds__(256)
k_edge2(const void* __restrict__ ei,
        const float* __restrict__ tt,
        const float* __restrict__ lu,
        const float4* __restrict__ msg4,
        const float* __restrict__ tw,
        const float* __restrict__ tb)
{
    const int w = threadIdx.x >> 5, lane = threadIdx.x & 31;
    const int dst = blockIdx.x * 8 + w;
    if (dst >= NN) return;
    const int is64 = g_is64;
    const int beg = g_off[dst], end = g_off[dst + 1];

    const int lq = lane & 15;
    const float4 tw4 = ((const float4*)tw)[lq];
    const float4 tb4 = ((const float4*)tb)[lq];
    const float4 q4 = g_q[(size_t)dst * 32 + lane];
    const size_t zb0 = (size_t)dst * 96;
    const float4 za = g_z[zb0 + lane];
    const float4 zb = g_z[zb0 + 32 + lane];
    const float4 zc = g_z[zb0 + 64 + lane];

    float4 aT = make_float4(0.f, 0.f, 0.f, 0.f), aV = aT, aM0 = aT, aM1 = aT;
    float s0 = 0.f, s1 = 0.f;

    for (int base = beg; base < end; base += 32) {
        const int cnt = min(32, end - base);
        int eidl = 0, srcl = 0; float rell = 0.f;
        if (lane < cnt) {
            eidl = g_eid[base + lane];
            long long s = is64 ? ((const long long*)ei)[eidl]
                               : (long long)((const int*)ei)[eidl];
            srcl = (int)s;
            rell = tt[eidl] - lu[s];
        }

        for (int j = 0; j < cnt; j++) {
            const int eid = __shfl_sync(0xffffffffu, eidl, j);
            const int src = __shfl_sync(0xffffffffu, srcl, j);
            const float rel = __shfl_sync(0xffffffffu, rell, j);

            const size_t mb = (size_t)eid * 32;
            float4 k4 = g_k[(size_t)src * 32 + lane];
            float4 v4 = g_v[(size_t)src * 32 + lane];
            float4 m4 = msg4[mb + lane];

            float4 ev;
            ev.x = __cosf(rel * tw4.x + tb4.x);
            ev.y = __cosf(rel * tw4.y + tb4.y);
            ev.z = __cosf(rel * tw4.z + tb4.z);
            ev.w = __cosf(rel * tw4.w + tb4.w);

            // fold q.k into head-resident lanes, then one pair of reductions
            float qk = dot4(q4, k4);
            float4 Aa = (lane < 16) ? ev : msg4[mb + lane - 16];
            float4 Ab = (lane < 16) ? msg4[mb + lane + 16] : ev;
            float pb = dot4(zb, Ab) + qk;
            float p0 = dot4(za, Aa) + ((lane < 16) ? pb : 0.f);
            float p1 = dot4(zc, m4) + ((lane < 16) ? 0.f : pb);
            #pragma unroll
            for (int o = 16; o >= 1; o >>= 1) {
                p0 += __shfl_xor_sync(0xffffffffu, p0, o);
                p1 += __shfl_xor_sync(0xffffffffu, p1, o);
            }

            float w0 = __expf(0.125f * p0);
            float w1 = __expf(0.125f * p1);

            float sc = (lane < 16) ? w0 : w1;
            aT.x += sc * ev.x; aT.y += sc * ev.y; aT.z += sc * ev.z; aT.w += sc * ev.w;
            aV.x += sc * v4.x; aV.y += sc * v4.y; aV.z += sc * v4.z; aV.w += sc * v4.w;
            aM0.x += w0 * m4.x; aM0.y += w0 * m4.y; aM0.z += w0 * m4.z; aM0.w += w0 * m4.w;
            aM1.x += w1 * m4.x; aM1.y += w1 * m4.y; aM1.z += w1 * m4.z; aM1.w += w1 * m4.w;
            s0 += w0; s1 += w1;
        }
    }

    g_aggT[(size_t)dst * 32 + lane] = aT;
    g_aggV[(size_t)dst * 32 + lane] = aV;
    g_aggM[(size_t)dst * 64 + lane]      = aM0;
    g_aggM[(size_t)dst * 64 + 32 + lane] = aM1;
    if (lane == 0) g_asum[dst] = make_float2(s0, s1);
}

// ---------------------------------------------------------------------------
// K3: out[n,h,c] += (aggV[n,h,c] + sum_d aggE[n,h,d]*We[d,h*64+c]) / asum[n,h]
// ---------------------------------------------------------------------------
__global__ void k_final(const float* __restrict__ We, float* __restrict__ out)
{
    extern __shared__ float sm[];
    float* WeS = sm;                 // 192 x 132
    float* sA  = sm + 192 * 132;     // 4 x 392
    float* sS  = sA + 4 * 392;       // 8 asums
    const int t = threadIdx.x;       // 128

    const float4* We4 = (const float4*)We;
    for (int i = t; i < 192 * 32; i += 128) {
        int d = i >> 5, c4 = i & 31;
        ((float4*)(WeS + d * 132))[c4] = We4[i];
    }

    const int j = t, h = t >> 6;
    for (int q0 = blockIdx.x * 4; q0 < NN; q0 += gridDim.x * 4) {
        __syncthreads();
        for (int i = t; i < 4 * 96; i += 128) {
            int ni = i / 96, m = i % 96;
            int node = q0 + ni;
            int hh = m / 48, d4 = m % 48;
            float4 val = (d4 < 16) ? g_aggT[(size_t)node * 32 + hh * 16 + d4]
                                   : g_aggM[(size_t)node * 64 + hh * 32 + (d4 - 16)];
            *(float4*)&sA[ni * 392 + hh * 196 + d4 * 4] = val;
        }
        if (t < 8) sS[t] = ((const float*)g_asum)[(size_t)(q0 + (t >> 1)) * 2 + (t & 1)];
        __syncthreads();

        float acc0 = 0.f, acc1 = 0.f, acc2 = 0.f, acc3 = 0.f;
        const float* a0 = sA + 0 * 392 + h * 196;
        const float* a1 = sA + 1 * 392 + h * 196;
        const float* a2 = sA + 2 * 392 + h * 196;
        const float* a3 = sA + 3 * 392 + h * 196;
        #pragma unroll 4
        for (int d = 0; d < 192; d++) {
            float wv = WeS[d * 132 + j];
            acc0 += wv * a0[d];
            acc1 += wv * a1[d];
            acc2 += wv * a2[d];
            acc3 += wv * a3[d];
        }

        const float* gv = (const float*)g_aggV;
        size_t n0 = (size_t)q0;
        out[(n0 + 0) * 128 + j] += (gv[(n0 + 0) * 128 + j] + acc0) * (1.f / (sS[0 + h] + 1e-16f));
        out[(n0 + 1) * 128 + j] += (gv[(n0 + 1) * 128 + j] + acc1) * (1.f / (sS[2 + h] + 1e-16f));
        out[(n0 + 2) * 128 + j] += (gv[(n0 + 2) * 128 + j] + acc2) * (1.f / (sS[4 + h] + 1e-16f));
        out[(n0 + 3) * 128 + j] += (gv[(n0 + 3) * 128 + j] + acc3) * (1.f / (sS[6 + h] + 1e-16f));
    }
}

// ---------------------------------------------------------------------------
extern "C" void kernel_launch(void* const* d_in, const int* in_sizes, int n_in,
                              void* d_out, int out_size)
{
    const float* x  = (const float*)d_in[0];
    const float* lu = (const float*)d_in[1];
    const float* tt = (const float*)d_in[2];
    const float* msg = (const float*)d_in[3];
    const float* tw = (const float*)d_in[4];
    const float* tb = (const float*)d_in[5];
    const float* Wq = (const float*)d_in[6];
    const float* bq = (const float*)d_in[7];
    const float* Wk = (const float*)d_in[8];
    const float* bk = (const float*)d_in[9];
    const float* Wv = (const float*)d_in[10];
    const float* bv = (const float*)d_in[11];
    const float* We = (const float*)d_in[12];
    const float* Ws = (const float*)d_in[13];
    const float* bs = (const float*)d_in[14];
    const void* ei  = d_in[15];
    float* out = (float*)d_out;

    cudaFuncSetAttribute(k_final, cudaFuncAttributeMaxDynamicSharedMemorySize, 107680);

    void* pcnt;
    cudaGetSymbolAddress(&pcnt, g_cnt);
    cudaMemsetAsync(pcnt, 0, NN * sizeof(int));

    const int NCHUNK = (NN + 511) / 512;   // 98

    k_detect<<<1, 1>>>((const int*)ei);
    k_prep<<<452, 256>>>(Wq, bq, Wk, bk, Wv, bv, Ws, bs, We);
    k_gemm<<<dim3(391, 7, 1), 256>>>(x, out);
    k_hist<<<(EE + 255) / 256, 256>>>(ei);
    k_scanA<<<NCHUNK, 512>>>();
    k_scanB<<<1, 32>>>(NCHUNK);
    k_scanC<<<NCHUNK, 512>>>();
    k_scatter<<<(EE + 255) / 256, 256>>>(ei);
    k_edge2<<<(NN + 7) / 8, 256>>>(ei, tt, lu, (const float4*)msg, tw, tb);
    k_final<<<592, 128, 107680>>>(We, out);
}